// round 7
// baseline (speedup 1.0000x reference)
#include <cuda_runtime.h>

#define GH 96
#define GW 96
#define HW (GH*GW)
#define BSZ 8
#define LN 16
#define PN 16
#define NCELL (BSZ*GH*GW)   /* 73728 */
#define TPB 128
#define CPB 64              /* cells per block; 2 threads per cell (p-split) */
#define NBLK (NCELL/CPB)    /* 1152 */

__device__ float g_partials[NBLK];
__device__ unsigned int g_ticket;   // zero-init; last block resets it

__device__ __forceinline__ float asqrt(float x) {
    float r;
    asm("sqrt.approx.f32 %0, %1;" : "=f"(r) : "f"(x));
    return r;
}

__global__ __launch_bounds__(TPB, 8)
void yolino_main(const float* __restrict__ target, const float* __restrict__ pred,
                 float* __restrict__ out)
{
    // Thread mapping: c = cell-in-block (0..63), half = which 8 predictors.
    // Warps 0-1: half 0 for cells 0..63; warps 2-3: half 1. Full coalescing.
    const int tid  = threadIdx.x;
    const int c    = tid & 63;
    const int half = tid >> 6;

    const int n  = blockIdx.x * CPB + c;   // grid cell
    const int w  = n % GW;
    const int t1 = n / GW;
    const int h  = t1 % GH;
    const int b  = t1 / GH;

    const int cell_off = h * GW + w;                    // within one channel plane
    const float* tb = target + b * (64 * HW) + cell_off;
    const float* pb = pred   + b * (96 * HW) + cell_off;

    // Shared target lines: stl[l][cell][coord], 16B per line -> LDS.128 reads.
    __shared__ __align__(16) float stl[LN][CPB][4];

    // Cooperative load: each thread loads 32 channels of ITS OWN cell
    // (half 0 -> even channels, half 1 -> odd). LDG coalesced across c.
    #pragma unroll
    for (int it = 0; it < 32; ++it) {
        const int ch = half + it * 2;          // 0..63
        stl[ch >> 2][c][ch & 3] = tb[ch * HW];
    }

    // Start predictor-0 prefetch before the barrier (independent of smem).
    const float* pbh = pb + (half * 8) * (6 * HW);
    float q0 = pbh[0], q1 = pbh[HW], q2 = pbh[2 * HW],
          q3 = pbh[3 * HW], q4 = pbh[4 * HW], q5 = pbh[5 * HW];

    __syncthreads();

    // Valid-line mask (each thread recomputes for its cell from smem).
    unsigned tmask = 0;
    #pragma unroll
    for (int l = 0; l < LN; ++l) {
        const float4 t4 = *reinterpret_cast<const float4*>(&stl[l][c][0]);
        float s = (t4.x + t4.y) + (t4.z + t4.w);
        if (s > 0.f) tmask |= (1u << l);
    }

    float loss = 0.f;

    #pragma unroll 1
    for (int pi = 0; pi < PN / 2; ++pi) {
        const float c0 = q0, c1 = q1, c2 = q2, c3 = q3, c4 = q4, c5 = q5;

        // Prefetch next predictor of this half.
        if (pi + 1 < PN / 2) {
            const float* nb = pbh + (pi + 1) * (6 * HW);
            q0 = nb[0];      q1 = nb[HW];     q2 = nb[2 * HW];
            q3 = nb[3 * HW]; q4 = nb[4 * HW]; q5 = nb[5 * HW];
        }

        // Pass 1: 16 independent distances (LDS.128 + 9 flops + 2 MUFU each).
        float d[LN];
        #pragma unroll
        for (int l = 0; l < LN; ++l) {
            const float4 t4 = *reinterpret_cast<const float4*>(&stl[l][c][0]);
            float dx1 = t4.x - c0, dy1 = t4.y - c1;
            float dx2 = t4.z - c2, dy2 = t4.w - c3;
            float s1 = fmaf(dx1, dx1, dy1 * dy1);
            float s2 = fmaf(dx2, dx2, dy2 * dy2);
            d[l] = asqrt(s1) + asqrt(s2);
        }

        // Pass 2: tree min (depth 4).
        float mm[8];
        #pragma unroll
        for (int i = 0; i < 8; ++i) mm[i] = fminf(d[2 * i], d[2 * i + 1]);
        #pragma unroll
        for (int i = 0; i < 4; ++i) mm[i] = fminf(mm[i], mm[i + 4]);
        mm[0] = fminf(mm[0], mm[2]);
        mm[1] = fminf(mm[1], mm[3]);
        const float m = fminf(mm[0], mm[1]);

        // Pass 3: tie mask (two independent OR chains).
        unsigned a0 = 0, a1 = 0;
        #pragma unroll
        for (int i = 0; i < 8; ++i) {
            a0 |= (d[i]     == m) ? (1u << i)       : 0u;
            a1 |= (d[i + 8] == m) ? (1u << (i + 8)) : 0u;
        }

        // thr = (m<2) ? m : -1; m >= 0 so thr=-1 selects nothing.
        const float cnt = (m < 2.f) ? (float)__popc((a0 | a1) & tmask) : 0.f;

        // dist term: selected entries all equal m.
        loss = fmaf(m, cnt, loss);

        // Confidence term.
        float sig = 1.f / (1.f + __expf(-c4));
        float e   = (cnt > 0.f) ? (sig - 1.f) : sig;
        loss = fmaf(e, e, loss);

        // Class term: cls_hard = 1 <=> c5 > 0.
        if (!(c5 > 0.f)) loss += cnt;
    }

    // ---- block reduction (deterministic) ----
    #pragma unroll
    for (int o = 16; o > 0; o >>= 1)
        loss += __shfl_xor_sync(0xffffffffu, loss, o);

    __shared__ float sw[TPB / 32];
    __shared__ bool  s_last;
    const int lane = tid & 31;
    const int wid  = tid >> 5;
    if (lane == 0) sw[wid] = loss;
    __syncthreads();
    if (wid == 0) {
        float v = (lane < TPB / 32) ? sw[lane] : 0.f;
        #pragma unroll
        for (int o = 2; o > 0; o >>= 1)
            v += __shfl_xor_sync(0xffffffffu, v, o);
        if (lane == 0) {
            g_partials[blockIdx.x] = v;
            __threadfence();
            unsigned t = atomicAdd(&g_ticket, 1u);
            s_last = (t == NBLK - 1);
        }
    }
    __syncthreads();

    // ---- last block folds all partials into the output ----
    if (s_last) {
        __threadfence();  // acquire: make all g_partials visible
        const int t = tid;
        float v = 0.f;
        for (int i = t; i < NBLK; i += TPB)   // fixed order: deterministic
            v += g_partials[i];
        __shared__ float s[TPB];
        s[t] = v;
        __syncthreads();
        #pragma unroll
        for (int o = TPB / 2; o > 0; o >>= 1) {
            if (t < o) s[t] += s[t + o];
            __syncthreads();
        }
        if (t == 0) {
            out[0] = s[0] * (1.0f / BSZ);
            g_ticket = 0;   // reset for the next (graph-replayed) launch
        }
    }
}

extern "C" void kernel_launch(void* const* d_in, const int* in_sizes, int n_in,
                              void* d_out, int out_size)
{
    const float* target = (const float*)d_in[0];
    const float* pred   = (const float*)d_in[1];
    float* out = (float*)d_out;

    yolino_main<<<NBLK, TPB>>>(target, pred, out);
}

// round 8
// speedup vs baseline: 1.3546x; 1.3546x over previous
#include <cuda_runtime.h>

#define GH 96
#define GW 96
#define HW (GH*GW)
#define BSZ 8
#define LN 16
#define PN 16
#define NCELL (BSZ*GH*GW)   /* 73728 */
#define TPB 128
#define NBLK (NCELL/TPB)    /* 576 */

__device__ float g_partials[NBLK];
__device__ unsigned int g_ticket;   // zero-init; last block resets it

__device__ __forceinline__ float asqrt(float x) {
    float r;
    asm("sqrt.approx.f32 %0, %1;" : "=f"(r) : "f"(x));
    return r;
}
__device__ __forceinline__ float arcp(float x) {
    float r;
    asm("rcp.approx.f32 %0, %1;" : "=f"(r) : "f"(x));
    return r;
}

__global__ __launch_bounds__(TPB, 4)
void yolino_main(const float* __restrict__ target, const float* __restrict__ pred,
                 float* __restrict__ out)
{
    const int n = blockIdx.x * TPB + threadIdx.x;   // n in [0, NCELL)
    const int w  = n % GW;
    const int t1 = n / GW;
    const int h  = t1 % GH;
    const int b  = t1 / GH;

    // 32-bit offsets (max ~7.1M elements < 2^31)
    const float* tb = target + b * (64 * HW) + h * GW + w;
    const float* pb = pred   + b * (96 * HW) + h * GW + w;

    // Load all 16 target lines (4 coords each) — coalesced across the warp.
    float tlv[LN][4];
    #pragma unroll
    for (int l = 0; l < LN; ++l) {
        #pragma unroll
        for (int j = 0; j < 4; ++j)
            tlv[l][j] = tb[(l * 4 + j) * HW];
    }

    // Valid-line mask: sum of the 4 coords > 0
    unsigned tmask = 0;
    #pragma unroll
    for (int l = 0; l < LN; ++l) {
        float s = (tlv[l][0] + tlv[l][1]) + (tlv[l][2] + tlv[l][3]);
        if (s > 0.f) tmask |= (1u << l);
    }

    float loss = 0.f;

    // Depth-2 rotating prefetch: q[0] holds predictor pi's channels when pi
    // is consumed, q[1] holds pi+1's. Slot (pi & 1) is refilled with pi+2.
    float q[2][6];
    #pragma unroll
    for (int s = 0; s < 2; ++s) {
        const float* nb = pb + s * (6 * HW);
        q[s][0] = nb[0];      q[s][1] = nb[HW];     q[s][2] = nb[2 * HW];
        q[s][3] = nb[3 * HW]; q[s][4] = nb[4 * HW]; q[s][5] = nb[5 * HW];
    }

    #pragma unroll 2
    for (int pi = 0; pi < PN; ++pi) {
        const int slot = pi & 1;                    // compile-time under unroll 2
        const float c0 = q[slot][0], c1 = q[slot][1], c2 = q[slot][2],
                    c3 = q[slot][3], c4 = q[slot][4], c5 = q[slot][5];

        // Refill consumed slot with predictor pi+2 (stays 2 iterations ahead).
        if (pi + 2 < PN) {
            const float* nb = pb + (pi + 2) * (6 * HW);
            q[slot][0] = nb[0];      q[slot][1] = nb[HW];
            q[slot][2] = nb[2 * HW]; q[slot][3] = nb[3 * HW];
            q[slot][4] = nb[4 * HW]; q[slot][5] = nb[5 * HW];
        }

        // Pass 1: 16 independent distances.
        float d[LN];
        #pragma unroll
        for (int l = 0; l < LN; ++l) {
            float dx1 = tlv[l][0] - c0, dy1 = tlv[l][1] - c1;
            float dx2 = tlv[l][2] - c2, dy2 = tlv[l][3] - c3;
            float s1 = fmaf(dx1, dx1, dy1 * dy1);
            float s2 = fmaf(dx2, dx2, dy2 * dy2);
            d[l] = asqrt(s1) + asqrt(s2);
        }

        // Pass 2: tree min (depth 4).
        float mm[8];
        #pragma unroll
        for (int i = 0; i < 8; ++i) mm[i] = fminf(d[2 * i], d[2 * i + 1]);
        #pragma unroll
        for (int i = 0; i < 4; ++i) mm[i] = fminf(mm[i], mm[i + 4]);
        mm[0] = fminf(mm[0], mm[2]);
        mm[1] = fminf(mm[1], mm[3]);
        const float m = fminf(mm[0], mm[1]);

        // Pass 3: tie mask (two independent OR chains).
        unsigned a0 = 0, a1 = 0;
        #pragma unroll
        for (int i = 0; i < 8; ++i) {
            a0 |= (d[i]     == m) ? (1u << i)       : 0u;
            a1 |= (d[i + 8] == m) ? (1u << (i + 8)) : 0u;
        }

        // thr = (m<2) ? m : -1; distances >= 0 so thr=-1 selects nothing.
        const float cnt = (m < 2.f) ? (float)__popc((a0 | a1) & tmask) : 0.f;

        // dist term: selected entries all equal m.
        loss = fmaf(m, cnt, loss);

        // Confidence term: sig = 1/(1+exp(-c4)) via approx exp + approx rcp.
        float sig = arcp(1.f + __expf(-c4));
        float e   = (cnt > 0.f) ? (sig - 1.f) : sig;
        loss = fmaf(e, e, loss);

        // Class term: cls_hard = 1 <=> c5 > 0.
        if (!(c5 > 0.f)) loss += cnt;
    }

    // ---- block reduction (deterministic) ----
    #pragma unroll
    for (int o = 16; o > 0; o >>= 1)
        loss += __shfl_xor_sync(0xffffffffu, loss, o);

    __shared__ float sw[TPB / 32];
    __shared__ bool  s_last;
    const int lane = threadIdx.x & 31;
    const int wid  = threadIdx.x >> 5;
    if (lane == 0) sw[wid] = loss;
    __syncthreads();
    if (wid == 0) {
        float v = (lane < TPB / 32) ? sw[lane] : 0.f;
        #pragma unroll
        for (int o = 2; o > 0; o >>= 1)
            v += __shfl_xor_sync(0xffffffffu, v, o);
        if (lane == 0) {
            g_partials[blockIdx.x] = v;
            __threadfence();
            unsigned t = atomicAdd(&g_ticket, 1u);
            s_last = (t == NBLK - 1);
        }
    }
    __syncthreads();

    // ---- last block folds all partials into the output ----
    if (s_last) {
        __threadfence();  // acquire: make all g_partials visible
        const int t = threadIdx.x;
        float v = 0.f;
        for (int i = t; i < NBLK; i += TPB)   // fixed order: deterministic
            v += g_partials[i];
        __shared__ float s[TPB];
        s[t] = v;
        __syncthreads();
        #pragma unroll
        for (int o = TPB / 2; o > 0; o >>= 1) {
            if (t < o) s[t] += s[t + o];
            __syncthreads();
        }
        if (t == 0) {
            out[0] = s[0] * (1.0f / BSZ);
            g_ticket = 0;   // reset for the next (graph-replayed) launch
        }
    }
}

extern "C" void kernel_launch(void* const* d_in, const int* in_sizes, int n_in,
                              void* d_out, int out_size)
{
    const float* target = (const float*)d_in[0];
    const float* pred   = (const float*)d_in[1];
    float* out = (float*)d_out;

    yolino_main<<<NBLK, TPB>>>(target, pred, out);
}